// round 1
// baseline (speedup 1.0000x reference)
#include <cuda_runtime.h>
#include <cstdint>

#define NE 262144
#define NT 1048576
#define H  128
#define IE 64
#define NR 6
#define NSR 42
#define BM 128          // edge rows per CTA in pre/post
#define TPB 512

// ---------------- scratch (static device allocations; no cudaMalloc) ----------
__device__ float g_Wrbf_eff[NR * H];                 // W_rbf1 @ W_rbf2
__device__ float g_dkj[(size_t)NE * IE];             // silu(x_kj@W_down+b)   [E,64]
__device__ float g_agg64[(size_t)NE * IE];           // segment_sum of triplets [E,64]
__device__ float g_xup[(size_t)NE * H];              // segment_sum of x1       [E,128]

__device__ __forceinline__ float silu_f(float x) { return x / (1.0f + __expf(-x)); }

// sm_90+ vector reduction (16B atomic add, no return)
__device__ __forceinline__ void red_add_v4(float* p, float4 v) {
    asm volatile("red.global.add.v4.f32 [%0], {%1, %2, %3, %4};"
                 :: "l"(p), "f"(v.x), "f"(v.y), "f"(v.z), "f"(v.w) : "memory");
}

// ---------------- small helpers ------------------------------------------------
__device__ __forceinline__ void copy_f4(float* dst, const float* __restrict__ src,
                                        int n4, int tid, int tpb) {
    for (int i = tid; i < n4; i += tpb)
        ((float4*)dst)[i] = __ldg((const float4*)src + i);
}

// out[r][c] = sum_k A[r][k] * W[k][c]; A pitch = H, W pitch = H.
// thread: 8 rows (r0..r0+7) x 4 cols (tx*4..+3). A-loads are warp-broadcast.
template <int K>
__device__ __forceinline__ void gemm_t(const float* __restrict__ A,
                                       const float* __restrict__ W,
                                       float acc[8][4], int r0, int tx) {
#pragma unroll
    for (int i = 0; i < 8; i++) { acc[i][0]=0.f; acc[i][1]=0.f; acc[i][2]=0.f; acc[i][3]=0.f; }
#pragma unroll 4
    for (int k = 0; k < K; k++) {
        const float4 b = *(const float4*)(W + k * H + (tx << 2));
#pragma unroll
        for (int i = 0; i < 8; i++) {
            const float a = A[(r0 + i) * H + k];
            acc[i][0] = fmaf(a, b.x, acc[i][0]);
            acc[i][1] = fmaf(a, b.y, acc[i][1]);
            acc[i][2] = fmaf(a, b.z, acc[i][2]);
            acc[i][3] = fmaf(a, b.w, acc[i][3]);
        }
    }
}

__device__ __forceinline__ void store_frag(float* As, float fr[8][4], int r0, int tx) {
#pragma unroll
    for (int i = 0; i < 8; i++)
        *(float4*)(As + (r0 + i) * H + (tx << 2)) =
            make_float4(fr[i][0], fr[i][1], fr[i][2], fr[i][3]);
}

// ---------------- kernel: zero accumulators ------------------------------------
__global__ void zero_kernel() {
    size_t idx = (size_t)blockIdx.x * blockDim.x + threadIdx.x;
    size_t step = (size_t)gridDim.x * blockDim.x;
    const float4 z = make_float4(0.f, 0.f, 0.f, 0.f);
    size_t n64 = (size_t)NE * IE / 4, n128 = (size_t)NE * H / 4;
    for (size_t i = idx; i < n64;  i += step) ((float4*)g_agg64)[i] = z;
    for (size_t i = idx; i < n128; i += step) ((float4*)g_xup)[i]   = z;
}

// ---------------- kernel: fold W_rbf1 @ W_rbf2 ---------------------------------
__global__ void wprep_kernel(const float* __restrict__ W_rbf1,
                             const float* __restrict__ W_rbf2) {
    int i = blockIdx.x * blockDim.x + threadIdx.x;
    if (i >= NR * H) return;
    int k = i >> 7, c = i & 127;
    float s = 0.f;
#pragma unroll
    for (int j = 0; j < 8; j++) s = fmaf(W_rbf1[k * 8 + j], W_rbf2[j * H + c], s);
    g_Wrbf_eff[i] = s;
}

// ---------------- kernel: edge pre  (x_kj -> g_dkj [E,64]) ---------------------
// smem: As[128*128] act | Ws[128*128] weights | rbs[128*6] | Wrb[6*128]
#define PRE_SMEM_BYTES ((128*128 + 128*128 + 128*6 + 6*128) * 4)
__global__ void __launch_bounds__(TPB, 1)
pre_kernel(const float* __restrict__ x_old, const float* __restrict__ rbf0,
           const float* __restrict__ W_kj, const float* __restrict__ b_kj,
           const float* __restrict__ W_down, const float* __restrict__ b_down) {
    extern __shared__ float sm[];
    float* As  = sm;
    float* Ws  = As + 128 * 128;
    float* rbs = Ws + 128 * 128;
    float* Wrb = rbs + 128 * 6;

    const int tid = threadIdx.x;
    const int ty = tid >> 5, tx = tid & 31;
    const int r0 = ty << 3;
    const long eb = (long)blockIdx.x * BM;

    copy_f4(As, x_old + eb * H, BM * H / 4, tid, TPB);
    copy_f4(Ws, W_kj, H * H / 4, tid, TPB);
    copy_f4(rbs, rbf0 + eb * NR, BM * NR / 4, tid, TPB);
    copy_f4(Wrb, g_Wrbf_eff, NR * H / 4, tid, TPB);
    __syncthreads();

    float acc[8][4];
    gemm_t<128>(As, Ws, acc, r0, tx);

    // epilogue: silu(+b_kj) * rbf  (rbf = rbf0 @ (W_rbf1@W_rbf2))
    {
        const float4 bv = *(const float4*)(b_kj + (tx << 2));
        float wc[NR][4];
#pragma unroll
        for (int l = 0; l < NR; l++) {
            float4 w4 = *(const float4*)(Wrb + l * H + (tx << 2));
            wc[l][0] = w4.x; wc[l][1] = w4.y; wc[l][2] = w4.z; wc[l][3] = w4.w;
        }
#pragma unroll
        for (int i = 0; i < 8; i++) {
            float rv0 = 0.f, rv1 = 0.f, rv2 = 0.f, rv3 = 0.f;
#pragma unroll
            for (int l = 0; l < NR; l++) {
                const float rb = rbs[(r0 + i) * NR + l];
                rv0 = fmaf(rb, wc[l][0], rv0); rv1 = fmaf(rb, wc[l][1], rv1);
                rv2 = fmaf(rb, wc[l][2], rv2); rv3 = fmaf(rb, wc[l][3], rv3);
            }
            acc[i][0] = silu_f(acc[i][0] + bv.x) * rv0;
            acc[i][1] = silu_f(acc[i][1] + bv.y) * rv1;
            acc[i][2] = silu_f(acc[i][2] + bv.z) * rv2;
            acc[i][3] = silu_f(acc[i][3] + bv.w) * rv3;
        }
    }
    __syncthreads();                 // all reads of As done
    store_frag(As, acc, r0, tx);     // write x_kj back as next act
    copy_f4(Ws, W_down, H * IE / 4, tid, TPB);   // [128,64]
    __syncthreads();

    // GEMM2: [128x128] @ [128x64] -> dkj
    float a2[8][2];
#pragma unroll
    for (int i = 0; i < 8; i++) { a2[i][0] = 0.f; a2[i][1] = 0.f; }
#pragma unroll 4
    for (int k = 0; k < 128; k++) {
        const float2 b = *(const float2*)(Ws + k * IE + (tx << 1));
#pragma unroll
        for (int i = 0; i < 8; i++) {
            const float a = As[(r0 + i) * H + k];
            a2[i][0] = fmaf(a, b.x, a2[i][0]);
            a2[i][1] = fmaf(a, b.y, a2[i][1]);
        }
    }
    const float2 bd = *(const float2*)(b_down + (tx << 1));
#pragma unroll
    for (int i = 0; i < 8; i++) {
        float2 o;
        o.x = silu_f(a2[i][0] + bd.x);
        o.y = silu_f(a2[i][1] + bd.y);
        *(float2*)(g_dkj + (eb + r0 + i) * IE + (tx << 1)) = o;
    }
}

// ---------------- kernel: triplets (sbf proj + gather*mul + scatter) -----------
__global__ void __launch_bounds__(256)
trip_kernel(const float* __restrict__ x1, const float* __restrict__ sbf,
            const int* __restrict__ idx_kj, const int* __restrict__ idx_ji,
            const float* __restrict__ W_sbf1, const float* __restrict__ W_sbf2) {
    __shared__ float sbfS[32 * NSR];   // 1344
    __shared__ float s8[32 * 8];
    __shared__ float Ws1[NSR * 8];     // 336
    __shared__ float Ws2[8 * IE];      // 512

    const int tid = threadIdx.x;
    const long tb = (long)blockIdx.x * 32;

    copy_f4(sbfS, sbf + tb * NSR, 32 * NSR / 4, tid, 256);
    copy_f4(Ws1, W_sbf1, NSR * 8 / 4, tid, 256);
    copy_f4(Ws2, W_sbf2, 8 * IE / 4, tid, 256);
    __syncthreads();

    const int trip = tid >> 3, j = tid & 7;
    const long t = tb + trip;

    // phase A: s8[trip][j] = sbf[t] . W_sbf1[:,j]
    {
        float s = 0.f;
#pragma unroll
        for (int i = 0; i < NSR; i++)
            s = fmaf(sbfS[trip * NSR + i], Ws1[i * 8 + j], s);
        s8[trip * 8 + j] = s;
    }
    __syncthreads();

    const int ik = idx_kj[t];
    const int ij = idx_ji[t];

    // phase B: p[c] = s8 . W_sbf2[:,c];  v = p * dkj[ik];  scatter into agg64[ij]
    {
        float sv[8];
#pragma unroll
        for (int jj = 0; jj < 8; jj++) sv[jj] = s8[trip * 8 + jj];
        const int c0 = j << 3;
        const float4 d0 = *(const float4*)(g_dkj + (long)ik * IE + c0);
        const float4 d1 = *(const float4*)(g_dkj + (long)ik * IE + c0 + 4);
        float p[8];
#pragma unroll
        for (int c = 0; c < 8; c++) {
            float s = 0.f;
#pragma unroll
            for (int jj = 0; jj < 8; jj++) s = fmaf(sv[jj], Ws2[jj * IE + c0 + c], s);
            p[c] = s;
        }
        red_add_v4(g_agg64 + (long)ij * IE + c0,
                   make_float4(p[0]*d0.x, p[1]*d0.y, p[2]*d0.z, p[3]*d0.w));
        red_add_v4(g_agg64 + (long)ij * IE + c0 + 4,
                   make_float4(p[4]*d1.x, p[5]*d1.y, p[6]*d1.z, p[7]*d1.w));
    }

    // phase C: x_up segment sum (16 cols per thread)
    {
        const int c1 = j << 4;
#pragma unroll
        for (int u = 0; u < 4; u++) {
            const float4 xv = *(const float4*)(x1 + t * H + c1 + (u << 2));
            red_add_v4(g_xup + (long)ij * H + c1 + (u << 2), xv);
        }
    }
}

// ---------------- kernel: fused edge post-chain --------------------------------
// smem: As | Xold | Ws | rbs | Wrb
#define POST_SMEM_BYTES ((128*128*3 + 128*6 + 6*128) * 4)

__device__ __forceinline__ void res_block(float* As, float* Ws,
                                          float frag[8][4], float acc[8][4],
                                          const float* __restrict__ Wg,
                                          const float* __restrict__ bg,
                                          int tid, int r0, int tx) {
    __syncthreads();
    store_frag(As, frag, r0, tx);
    copy_f4(Ws, Wg, H * H / 4, tid, TPB);
    __syncthreads();
    gemm_t<128>(As, Ws, acc, r0, tx);
    const float4 b0 = *(const float4*)(bg + (tx << 2));
    __syncthreads();                               // all reads of As done
#pragma unroll
    for (int i = 0; i < 8; i++) {
        float4 hv;
        hv.x = silu_f(acc[i][0] + b0.x);
        hv.y = silu_f(acc[i][1] + b0.y);
        hv.z = silu_f(acc[i][2] + b0.z);
        hv.w = silu_f(acc[i][3] + b0.w);
        *(float4*)(As + (r0 + i) * H + (tx << 2)) = hv;
    }
    copy_f4(Ws, Wg + H * H, H * H / 4, tid, TPB);
    __syncthreads();
    gemm_t<128>(As, Ws, acc, r0, tx);
    const float4 b1 = *(const float4*)(bg + H + (tx << 2));
#pragma unroll
    for (int i = 0; i < 8; i++) {
        frag[i][0] += silu_f(acc[i][0] + b1.x);
        frag[i][1] += silu_f(acc[i][1] + b1.y);
        frag[i][2] += silu_f(acc[i][2] + b1.z);
        frag[i][3] += silu_f(acc[i][3] + b1.w);
    }
}

__global__ void __launch_bounds__(TPB, 1)
post_kernel(const float* __restrict__ x_old, const float* __restrict__ rbf0,
            const float* __restrict__ W_ji, const float* __restrict__ b_ji,
            const float* __restrict__ W_up, const float* __restrict__ b_up,
            const float* __restrict__ W_connect, const float* __restrict__ b_connect,
            const float* __restrict__ W_get_up, const float* __restrict__ b_get_up,
            const float* __restrict__ res_before_W, const float* __restrict__ res_before_b,
            const float* __restrict__ W_lin, const float* __restrict__ b_lin,
            const float* __restrict__ res_after_W, const float* __restrict__ res_after_b,
            const float* __restrict__ W_rbf, float* __restrict__ out) {
    extern __shared__ float sm[];
    float* As   = sm;
    float* Xold = As + 128 * 128;
    float* Ws   = Xold + 128 * 128;
    float* rbs  = Ws + 128 * 128;
    float* Wrb  = rbs + 128 * 6;

    const int tid = threadIdx.x;
    const int ty = tid >> 5, tx = tid & 31;
    const int r0 = ty << 3;
    const long eb = (long)blockIdx.x * BM;

    copy_f4(Xold, x_old + eb * H, BM * H / 4, tid, TPB);
    copy_f4(rbs, rbf0 + eb * NR, BM * NR / 4, tid, TPB);
    copy_f4(Wrb, W_rbf, NR * H / 4, tid, TPB);
    copy_f4(Ws, W_ji, H * H / 4, tid, TPB);
    __syncthreads();

    float frag[8][4], acc[8][4];

    // S0: x_ji = silu(x_old @ W_ji + b)
    gemm_t<128>(Xold, Ws, acc, r0, tx);
    {
        const float4 b = *(const float4*)(b_ji + (tx << 2));
#pragma unroll
        for (int i = 0; i < 8; i++) {
            frag[i][0] = silu_f(acc[i][0] + b.x);
            frag[i][1] = silu_f(acc[i][1] + b.y);
            frag[i][2] = silu_f(acc[i][2] + b.z);
            frag[i][3] = silu_f(acc[i][3] + b.w);
        }
    }

    // S1: += silu(agg64 @ W_up + b)
    __syncthreads();
    for (int i = tid; i < BM * (IE / 4); i += TPB) {
        int r = i >> 4, c = (i & 15) << 2;
        *(float4*)(As + r * H + c) = *(const float4*)(g_agg64 + (eb + r) * IE + c);
    }
    copy_f4(Ws, W_up, IE * H / 4, tid, TPB);
    __syncthreads();
    gemm_t<64>(As, Ws, acc, r0, tx);
    {
        const float4 b = *(const float4*)(b_up + (tx << 2));
#pragma unroll
        for (int i = 0; i < 8; i++) {
            frag[i][0] += silu_f(acc[i][0] + b.x);
            frag[i][1] += silu_f(acc[i][1] + b.y);
            frag[i][2] += silu_f(acc[i][2] + b.z);
            frag[i][3] += silu_f(acc[i][3] + b.w);
        }
    }

    // S2: e1 = silu(e1 @ W_connect + b)
    __syncthreads();
    store_frag(As, frag, r0, tx);
    copy_f4(Ws, W_connect, H * H / 4, tid, TPB);
    __syncthreads();
    gemm_t<128>(As, Ws, acc, r0, tx);
    {
        const float4 b = *(const float4*)(b_connect + (tx << 2));
#pragma unroll
        for (int i = 0; i < 8; i++) {
            frag[i][0] = silu_f(acc[i][0] + b.x);
            frag[i][1] = silu_f(acc[i][1] + b.y);
            frag[i][2] = silu_f(acc[i][2] + b.z);
            frag[i][3] = silu_f(acc[i][3] + b.w);
        }
    }

    // S3: += x_up = silu(xup_agg @ W_get_up + b)
    __syncthreads();
    copy_f4(As, g_xup + eb * H, BM * H / 4, tid, TPB);
    copy_f4(Ws, W_get_up, H * H / 4, tid, TPB);
    __syncthreads();
    gemm_t<128>(As, Ws, acc, r0, tx);
    {
        const float4 b = *(const float4*)(b_get_up + (tx << 2));
#pragma unroll
        for (int i = 0; i < 8; i++) {
            frag[i][0] += silu_f(acc[i][0] + b.x);
            frag[i][1] += silu_f(acc[i][1] + b.y);
            frag[i][2] += silu_f(acc[i][2] + b.z);
            frag[i][3] += silu_f(acc[i][3] + b.w);
        }
    }

    // S4: res_before[0]
    res_block(As, Ws, frag, acc, res_before_W, res_before_b, tid, r0, tx);

    // S5: e1 = silu(e1 @ W_lin + b) + x_old
    __syncthreads();
    store_frag(As, frag, r0, tx);
    copy_f4(Ws, W_lin, H * H / 4, tid, TPB);
    __syncthreads();
    gemm_t<128>(As, Ws, acc, r0, tx);
    {
        const float4 b = *(const float4*)(b_lin + (tx << 2));
#pragma unroll
        for (int i = 0; i < 8; i++) {
            const float4 xo = *(const float4*)(Xold + (r0 + i) * H + (tx << 2));
            frag[i][0] = silu_f(acc[i][0] + b.x) + xo.x;
            frag[i][1] = silu_f(acc[i][1] + b.y) + xo.y;
            frag[i][2] = silu_f(acc[i][2] + b.z) + xo.z;
            frag[i][3] = silu_f(acc[i][3] + b.w) + xo.w;
        }
    }

    // S6/S7: res_after[0], res_after[1]
    res_block(As, Ws, frag, acc, res_after_W,             res_after_b,         tid, r0, tx);
    res_block(As, Ws, frag, acc, res_after_W + 2 * H * H, res_after_b + 2 * H, tid, r0, tx);

    // S8: write e1; e2 = (rbf0 @ W_rbf) * e1
    {
        const long EH = (long)NE * H;
        float wc[NR][4];
#pragma unroll
        for (int l = 0; l < NR; l++) {
            float4 w4 = *(const float4*)(Wrb + l * H + (tx << 2));
            wc[l][0] = w4.x; wc[l][1] = w4.y; wc[l][2] = w4.z; wc[l][3] = w4.w;
        }
#pragma unroll
        for (int i = 0; i < 8; i++) {
            const long row = (eb + r0 + i) * H + (tx << 2);
            *(float4*)(out + row) = make_float4(frag[i][0], frag[i][1], frag[i][2], frag[i][3]);
            float rv0 = 0.f, rv1 = 0.f, rv2 = 0.f, rv3 = 0.f;
#pragma unroll
            for (int l = 0; l < NR; l++) {
                const float rb = rbs[(r0 + i) * NR + l];
                rv0 = fmaf(rb, wc[l][0], rv0); rv1 = fmaf(rb, wc[l][1], rv1);
                rv2 = fmaf(rb, wc[l][2], rv2); rv3 = fmaf(rb, wc[l][3], rv3);
            }
            *(float4*)(out + EH + row) =
                make_float4(rv0 * frag[i][0], rv1 * frag[i][1], rv2 * frag[i][2], rv3 * frag[i][3]);
        }
    }
}

// ---------------- launch --------------------------------------------------------
extern "C" void kernel_launch(void* const* d_in, const int* in_sizes, int n_in,
                              void* d_out, int out_size) {
    const float* x1           = (const float*)d_in[0];
    const float* x_old        = (const float*)d_in[1];
    const float* rbf0         = (const float*)d_in[2];
    const float* sbf          = (const float*)d_in[3];
    const int*   idx_kj       = (const int*)d_in[4];
    const int*   idx_ji       = (const int*)d_in[5];
    const float* W_rbf1       = (const float*)d_in[6];
    const float* W_rbf2       = (const float*)d_in[7];
    const float* W_sbf1       = (const float*)d_in[8];
    const float* W_sbf2       = (const float*)d_in[9];
    const float* W_rbf        = (const float*)d_in[10];
    const float* W_kj         = (const float*)d_in[11];
    const float* b_kj         = (const float*)d_in[12];
    const float* W_ji         = (const float*)d_in[13];
    const float* b_ji         = (const float*)d_in[14];
    const float* W_connect    = (const float*)d_in[15];
    const float* b_connect    = (const float*)d_in[16];
    const float* W_get_up     = (const float*)d_in[17];
    const float* b_get_up     = (const float*)d_in[18];
    const float* W_down       = (const float*)d_in[19];
    const float* b_down       = (const float*)d_in[20];
    const float* W_up         = (const float*)d_in[21];
    const float* b_up         = (const float*)d_in[22];
    const float* res_before_W = (const float*)d_in[23];
    const float* res_before_b = (const float*)d_in[24];
    const float* W_lin        = (const float*)d_in[25];
    const float* b_lin        = (const float*)d_in[26];
    const float* res_after_W  = (const float*)d_in[27];
    const float* res_after_b  = (const float*)d_in[28];
    float* out = (float*)d_out;

    cudaFuncSetAttribute(pre_kernel,  cudaFuncAttributeMaxDynamicSharedMemorySize, PRE_SMEM_BYTES);
    cudaFuncSetAttribute(post_kernel, cudaFuncAttributeMaxDynamicSharedMemorySize, POST_SMEM_BYTES);

    zero_kernel<<<4096, 256>>>();
    wprep_kernel<<<3, 256>>>(W_rbf1, W_rbf2);
    pre_kernel<<<NE / BM, TPB, PRE_SMEM_BYTES>>>(x_old, rbf0, W_kj, b_kj, W_down, b_down);
    trip_kernel<<<NT / 32, 256>>>(x1, sbf, idx_kj, idx_ji, W_sbf1, W_sbf2);
    post_kernel<<<NE / BM, TPB, POST_SMEM_BYTES>>>(
        x_old, rbf0, W_ji, b_ji, W_up, b_up, W_connect, b_connect,
        W_get_up, b_get_up, res_before_W, res_before_b, W_lin, b_lin,
        res_after_W, res_after_b, W_rbf, out);
}

// round 2
// speedup vs baseline: 1.5860x; 1.5860x over previous
#include <cuda_runtime.h>
#include <cstdint>

#define NE 262144
#define NT 1048576
#define H  128
#define IE 64
#define NR 6
#define NSR 42
#define BM 128
#define TPB 512
#define PA 132     // smem pitch (floats/uints) for MMA tiles

// ---------------- scratch (static device allocations) --------------------------
__device__ float g_Wrbf_eff[NR * H];
__device__ float g_dkj[(size_t)NE * IE];
__device__ float g_agg64[(size_t)NE * IE];
__device__ float g_xup[(size_t)NE * H];

__device__ __forceinline__ float silu_f(float x) { return x / (1.0f + __expf(-x)); }

__device__ __forceinline__ unsigned f2tf32(float x) {
    unsigned u; asm("cvt.rna.tf32.f32 %0, %1;" : "=r"(u) : "f"(x)); return u;
}

__device__ __forceinline__ void red_add_v4(float* p, float4 v) {
    asm volatile("red.global.add.v4.f32 [%0], {%1, %2, %3, %4};"
                 :: "l"(p), "f"(v.x), "f"(v.y), "f"(v.z), "f"(v.w) : "memory");
}

__device__ __forceinline__ void mma8(float c[4], const unsigned a[4], const unsigned b[2]) {
    asm volatile("mma.sync.aligned.m16n8k8.row.col.f32.tf32.tf32.f32 "
                 "{%0,%1,%2,%3}, {%4,%5,%6,%7}, {%8,%9}, {%0,%1,%2,%3};"
                 : "+f"(c[0]), "+f"(c[1]), "+f"(c[2]), "+f"(c[3])
                 : "r"(a[0]), "r"(a[1]), "r"(a[2]), "r"(a[3]), "r"(b[0]), "r"(b[1]));
}

// GEMM on tensor cores: acc[128x(NFR*8*4)] tile, A in As (pitch PA, tf32 bits),
// W row-major [k][n] in Ws (pitch PA, tf32 bits). Warp (wm, wn) owns rows
// [wm*32, +32), cols [wn*NFR*8, +NFR*8).
template <int KS, int NFR>
__device__ __forceinline__ void gemm_mma(const unsigned* __restrict__ As,
                                         const unsigned* __restrict__ Ws,
                                         float acc[2][4][4], int wm, int wn, int lane) {
    const int qid = lane >> 2, ql = lane & 3;
#pragma unroll
    for (int mi = 0; mi < 2; mi++)
#pragma unroll
        for (int ni = 0; ni < NFR; ni++)
#pragma unroll
            for (int j = 0; j < 4; j++) acc[mi][ni][j] = 0.f;

    const unsigned* Abase = As + (wm * 32 + qid) * PA + ql;
    const unsigned* Bbase = Ws + ql * PA + wn * (NFR * 8) + qid;
#pragma unroll
    for (int kk = 0; kk < KS; kk++) {
        const int k0 = kk * 8;
        unsigned a[2][4], b[4][2];
#pragma unroll
        for (int mi = 0; mi < 2; mi++) {
            const unsigned* p = Abase + mi * 16 * PA + k0;
            a[mi][0] = p[0];
            a[mi][1] = p[8 * PA];
            a[mi][2] = p[4];
            a[mi][3] = p[8 * PA + 4];
        }
#pragma unroll
        for (int ni = 0; ni < NFR; ni++) {
            const unsigned* p = Bbase + k0 * PA + ni * 8;
            b[ni][0] = p[0];
            b[ni][1] = p[4 * PA];
        }
#pragma unroll
        for (int mi = 0; mi < 2; mi++)
#pragma unroll
            for (int ni = 0; ni < NFR; ni++) mma8(acc[mi][ni], a[mi], b[ni]);
    }
}

// stage fp32 global (row-major, pitch COLS) -> smem tf32 bits (pitch PA)
template <int COLS>
__device__ __forceinline__ void stage_tf32(unsigned* dst, const float* __restrict__ src,
                                           int rows, int tid) {
    const int c4 = COLS >> 2;
    for (int i = tid; i < rows * c4; i += TPB) {
        const int r = i / c4, c = (i - r * c4) << 2;
        float4 v = __ldg((const float4*)src + i);
        *(uint4*)(dst + r * PA + c) =
            make_uint4(f2tf32(v.x), f2tf32(v.y), f2tf32(v.z), f2tf32(v.w));
    }
}

// store fp32 fragment tile -> smem tf32 A tile (pitch PA)
__device__ __forceinline__ void store_frag_tf32(unsigned* As, float fr[2][4][4],
                                                int wm, int wn, int lane) {
    const int qid = lane >> 2, ql = lane & 3;
#pragma unroll
    for (int mi = 0; mi < 2; mi++) {
        const int r0 = wm * 32 + mi * 16 + qid;
#pragma unroll
        for (int ni = 0; ni < 4; ni++) {
            const int c = wn * 32 + ni * 8 + ql * 2;
            *(uint2*)(As + r0 * PA + c) =
                make_uint2(f2tf32(fr[mi][ni][0]), f2tf32(fr[mi][ni][1]));
            *(uint2*)(As + (r0 + 8) * PA + c) =
                make_uint2(f2tf32(fr[mi][ni][2]), f2tf32(fr[mi][ni][3]));
        }
    }
}

__device__ __forceinline__ void copy_f4(float* dst, const float* __restrict__ src,
                                        int n4, int tid, int tpb) {
    for (int i = tid; i < n4; i += tpb)
        ((float4*)dst)[i] = __ldg((const float4*)src + i);
}

// ---------------- kernel: zero accumulators ------------------------------------
__global__ void zero_kernel() {
    size_t idx = (size_t)blockIdx.x * blockDim.x + threadIdx.x;
    size_t step = (size_t)gridDim.x * blockDim.x;
    const float4 z = make_float4(0.f, 0.f, 0.f, 0.f);
    size_t n64 = (size_t)NE * IE / 4, n128 = (size_t)NE * H / 4;
    for (size_t i = idx; i < n64;  i += step) ((float4*)g_agg64)[i] = z;
    for (size_t i = idx; i < n128; i += step) ((float4*)g_xup)[i]   = z;
}

// ---------------- kernel: fold W_rbf1 @ W_rbf2 ---------------------------------
__global__ void wprep_kernel(const float* __restrict__ W_rbf1,
                             const float* __restrict__ W_rbf2) {
    int i = blockIdx.x * blockDim.x + threadIdx.x;
    if (i >= NR * H) return;
    int k = i >> 7, c = i & 127;
    float s = 0.f;
#pragma unroll
    for (int j = 0; j < 8; j++) s = fmaf(W_rbf1[k * 8 + j], W_rbf2[j * H + c], s);
    g_Wrbf_eff[i] = s;
}

// ---------------- kernel: edge pre (tensorized) --------------------------------
#define PRE_SMEM ((128 * PA + 128 * PA + 128 * 8 + 8 * 128) * 4)
__global__ void __launch_bounds__(TPB, 1)
pre_kernel(const float* __restrict__ x_old, const float* __restrict__ rbf0,
           const float* __restrict__ W_kj, const float* __restrict__ b_kj,
           const float* __restrict__ W_down, const float* __restrict__ b_down) {
    extern __shared__ unsigned sm_u[];
    unsigned* As = sm_u;
    unsigned* Ws = As + 128 * PA;
    float* rbs = (float*)(Ws + 128 * PA);     // [128][8]
    float* Wrb = rbs + 128 * 8;               // [6][128]

    const int tid = threadIdx.x, lane = tid & 31, wid = tid >> 5;
    const int wm = wid >> 2, wn = wid & 3;
    const int qid = lane >> 2, ql = lane & 3;
    const long eb = (long)blockIdx.x * BM;

    stage_tf32<128>(As, x_old + eb * H, 128, tid);
    stage_tf32<128>(Ws, W_kj, 128, tid);
    for (int i = tid; i < 128 * NR; i += TPB)
        rbs[(i / NR) * 8 + (i % NR)] = __ldg(rbf0 + eb * NR + i);
    copy_f4(Wrb, g_Wrbf_eff, NR * H / 4, tid, TPB);
    __syncthreads();

    float acc[2][4][4];
    gemm_mma<16, 4>(As, Ws, acc, wm, wn, lane);

    // epilogue: silu(+b_kj) * (rbf0 @ Wrbf_eff)
#pragma unroll
    for (int mi = 0; mi < 2; mi++) {
        const int r0 = wm * 32 + mi * 16 + qid;
#pragma unroll
        for (int ni = 0; ni < 4; ni++) {
            const int c = wn * 32 + ni * 8 + ql * 2;
            const float2 bv = __ldg((const float2*)(b_kj + c));
            float rv[2][2] = {{0.f, 0.f}, {0.f, 0.f}};
#pragma unroll
            for (int l = 0; l < NR; l++) {
                const float w0 = Wrb[l * 128 + c], w1 = Wrb[l * 128 + c + 1];
                const float rA = rbs[r0 * 8 + l], rB = rbs[(r0 + 8) * 8 + l];
                rv[0][0] = fmaf(rA, w0, rv[0][0]); rv[0][1] = fmaf(rA, w1, rv[0][1]);
                rv[1][0] = fmaf(rB, w0, rv[1][0]); rv[1][1] = fmaf(rB, w1, rv[1][1]);
            }
            acc[mi][ni][0] = silu_f(acc[mi][ni][0] + bv.x) * rv[0][0];
            acc[mi][ni][1] = silu_f(acc[mi][ni][1] + bv.y) * rv[0][1];
            acc[mi][ni][2] = silu_f(acc[mi][ni][2] + bv.x) * rv[1][0];
            acc[mi][ni][3] = silu_f(acc[mi][ni][3] + bv.y) * rv[1][1];
        }
    }
    __syncthreads();
    store_frag_tf32(As, acc, wm, wn, lane);
    stage_tf32<64>(Ws, W_down, 128, tid);
    __syncthreads();

    gemm_mma<16, 2>(As, Ws, acc, wm, wn, lane);
#pragma unroll
    for (int mi = 0; mi < 2; mi++) {
        const int r0 = wm * 32 + mi * 16 + qid;
#pragma unroll
        for (int ni = 0; ni < 2; ni++) {
            const int c = wn * 16 + ni * 8 + ql * 2;
            const float2 bv = __ldg((const float2*)(b_down + c));
            float2 o0, o1;
            o0.x = silu_f(acc[mi][ni][0] + bv.x);
            o0.y = silu_f(acc[mi][ni][1] + bv.y);
            o1.x = silu_f(acc[mi][ni][2] + bv.x);
            o1.y = silu_f(acc[mi][ni][3] + bv.y);
            *(float2*)(g_dkj + (eb + r0) * IE + c)     = o0;
            *(float2*)(g_dkj + (eb + r0 + 8) * IE + c) = o1;
        }
    }
}

// ---------------- kernel: triplets (unchanged — near its roofline) -------------
__global__ void __launch_bounds__(256)
trip_kernel(const float* __restrict__ x1, const float* __restrict__ sbf,
            const int* __restrict__ idx_kj, const int* __restrict__ idx_ji,
            const float* __restrict__ W_sbf1, const float* __restrict__ W_sbf2) {
    __shared__ float sbfS[32 * NSR];
    __shared__ float s8[32 * 8];
    __shared__ float Ws1[NSR * 8];
    __shared__ float Ws2[8 * IE];

    const int tid = threadIdx.x;
    const long tb = (long)blockIdx.x * 32;

    copy_f4(sbfS, sbf + tb * NSR, 32 * NSR / 4, tid, 256);
    copy_f4(Ws1, W_sbf1, NSR * 8 / 4, tid, 256);
    copy_f4(Ws2, W_sbf2, 8 * IE / 4, tid, 256);
    __syncthreads();

    const int trip = tid >> 3, j = tid & 7;
    const long t = tb + trip;

    {
        float s = 0.f;
#pragma unroll
        for (int i = 0; i < NSR; i++)
            s = fmaf(sbfS[trip * NSR + i], Ws1[i * 8 + j], s);
        s8[trip * 8 + j] = s;
    }
    __syncthreads();

    const int ik = idx_kj[t];
    const int ij = idx_ji[t];

    {
        float sv[8];
#pragma unroll
        for (int jj = 0; jj < 8; jj++) sv[jj] = s8[trip * 8 + jj];
        const int c0 = j << 3;
        const float4 d0 = *(const float4*)(g_dkj + (long)ik * IE + c0);
        const float4 d1 = *(const float4*)(g_dkj + (long)ik * IE + c0 + 4);
        float p[8];
#pragma unroll
        for (int c = 0; c < 8; c++) {
            float s = 0.f;
#pragma unroll
            for (int jj = 0; jj < 8; jj++) s = fmaf(sv[jj], Ws2[jj * IE + c0 + c], s);
            p[c] = s;
        }
        red_add_v4(g_agg64 + (long)ij * IE + c0,
                   make_float4(p[0]*d0.x, p[1]*d0.y, p[2]*d0.z, p[3]*d0.w));
        red_add_v4(g_agg64 + (long)ij * IE + c0 + 4,
                   make_float4(p[4]*d1.x, p[5]*d1.y, p[6]*d1.z, p[7]*d1.w));
    }

    {
        const int c1 = j << 4;
#pragma unroll
        for (int u = 0; u < 4; u++) {
            const float4 xv = *(const float4*)(x1 + t * H + c1 + (u << 2));
            red_add_v4(g_xup + (long)ij * H + c1 + (u << 2), xv);
        }
    }
}

// ---------------- kernel: fused edge post-chain (tensorized) -------------------
#define POST_SMEM ((128 * PA * 3 + 128 * 8 + 8 * 128) * 4)

__global__ void __launch_bounds__(TPB, 1)
post_kernel(const float* __restrict__ x_old, const float* __restrict__ rbf0,
            const float* __restrict__ W_ji, const float* __restrict__ b_ji,
            const float* __restrict__ W_up, const float* __restrict__ b_up,
            const float* __restrict__ W_connect, const float* __restrict__ b_connect,
            const float* __restrict__ W_get_up, const float* __restrict__ b_get_up,
            const float* __restrict__ res_before_W, const float* __restrict__ res_before_b,
            const float* __restrict__ W_lin, const float* __restrict__ b_lin,
            const float* __restrict__ res_after_W, const float* __restrict__ res_after_b,
            const float* __restrict__ W_rbf, float* __restrict__ out) {
    extern __shared__ unsigned sm_u[];
    unsigned* As = sm_u;
    unsigned* Ws = As + 128 * PA;
    float* Xold = (float*)(Ws + 128 * PA);    // [128][PA] fp32
    float* rbs = Xold + 128 * PA;             // [128][8]
    float* Wrb = rbs + 128 * 8;               // [6][128]

    const int tid = threadIdx.x, lane = tid & 31, wid = tid >> 5;
    const int wm = wid >> 2, wn = wid & 3;
    const int qid = lane >> 2, ql = lane & 3;
    const long eb = (long)blockIdx.x * BM;

    // ---- stage inputs for S0
    stage_tf32<128>(As, x_old + eb * H, 128, tid);
    stage_tf32<128>(Ws, W_ji, 128, tid);
    for (int i = tid; i < 128 * 32; i += TPB) {
        const int r = i >> 5, c = (i & 31) << 2;
        *(float4*)(Xold + r * PA + c) = __ldg((const float4*)(x_old + (eb + r) * H + c));
    }
    for (int i = tid; i < 128 * NR; i += TPB)
        rbs[(i / NR) * 8 + (i % NR)] = __ldg(rbf0 + eb * NR + i);
    copy_f4(Wrb, W_rbf, NR * H / 4, tid, TPB);
    __syncthreads();

    float frag[2][4][4], acc[2][4][4];

    // S0: x_ji = silu(x_old @ W_ji + b)
    gemm_mma<16, 4>(As, Ws, acc, wm, wn, lane);
#pragma unroll
    for (int mi = 0; mi < 2; mi++)
#pragma unroll
        for (int ni = 0; ni < 4; ni++) {
            const int c = wn * 32 + ni * 8 + ql * 2;
            const float2 bv = __ldg((const float2*)(b_ji + c));
            frag[mi][ni][0] = silu_f(acc[mi][ni][0] + bv.x);
            frag[mi][ni][1] = silu_f(acc[mi][ni][1] + bv.y);
            frag[mi][ni][2] = silu_f(acc[mi][ni][2] + bv.x);
            frag[mi][ni][3] = silu_f(acc[mi][ni][3] + bv.y);
        }

    // S1: += silu(agg64 @ W_up + b)
    __syncthreads();
    stage_tf32<64>(As, g_agg64 + eb * IE, 128, tid);
    stage_tf32<128>(Ws, W_up, 64, tid);
    __syncthreads();
    gemm_mma<8, 4>(As, Ws, acc, wm, wn, lane);
#pragma unroll
    for (int mi = 0; mi < 2; mi++)
#pragma unroll
        for (int ni = 0; ni < 4; ni++) {
            const int c = wn * 32 + ni * 8 + ql * 2;
            const float2 bv = __ldg((const float2*)(b_up + c));
            frag[mi][ni][0] += silu_f(acc[mi][ni][0] + bv.x);
            frag[mi][ni][1] += silu_f(acc[mi][ni][1] + bv.y);
            frag[mi][ni][2] += silu_f(acc[mi][ni][2] + bv.x);
            frag[mi][ni][3] += silu_f(acc[mi][ni][3] + bv.y);
        }

    // S2: e1 = silu(e1 @ W_connect + b)
    __syncthreads();
    store_frag_tf32(As, frag, wm, wn, lane);
    stage_tf32<128>(Ws, W_connect, 128, tid);
    __syncthreads();
    gemm_mma<16, 4>(As, Ws, acc, wm, wn, lane);
#pragma unroll
    for (int mi = 0; mi < 2; mi++)
#pragma unroll
        for (int ni = 0; ni < 4; ni++) {
            const int c = wn * 32 + ni * 8 + ql * 2;
            const float2 bv = __ldg((const float2*)(b_connect + c));
            frag[mi][ni][0] = silu_f(acc[mi][ni][0] + bv.x);
            frag[mi][ni][1] = silu_f(acc[mi][ni][1] + bv.y);
            frag[mi][ni][2] = silu_f(acc[mi][ni][2] + bv.x);
            frag[mi][ni][3] = silu_f(acc[mi][ni][3] + bv.y);
        }

    // S3: += silu(xup @ W_get_up + b)
    __syncthreads();
    stage_tf32<128>(As, g_xup + eb * H, 128, tid);
    stage_tf32<128>(Ws, W_get_up, 128, tid);
    __syncthreads();
    gemm_mma<16, 4>(As, Ws, acc, wm, wn, lane);
#pragma unroll
    for (int mi = 0; mi < 2; mi++)
#pragma unroll
        for (int ni = 0; ni < 4; ni++) {
            const int c = wn * 32 + ni * 8 + ql * 2;
            const float2 bv = __ldg((const float2*)(b_get_up + c));
            frag[mi][ni][0] += silu_f(acc[mi][ni][0] + bv.x);
            frag[mi][ni][1] += silu_f(acc[mi][ni][1] + bv.y);
            frag[mi][ni][2] += silu_f(acc[mi][ni][2] + bv.x);
            frag[mi][ni][3] += silu_f(acc[mi][ni][3] + bv.y);
        }

    // residual blocks: frag += silu(lin2(silu(lin1(frag))))
#define RES_BLOCK(Wg, bg)                                                          \
    {                                                                              \
        __syncthreads();                                                           \
        store_frag_tf32(As, frag, wm, wn, lane);                                   \
        stage_tf32<128>(Ws, (Wg), 128, tid);                                       \
        __syncthreads();                                                           \
        gemm_mma<16, 4>(As, Ws, acc, wm, wn, lane);                                \
        _Pragma("unroll")                                                          \
        for (int mi = 0; mi < 2; mi++)                                             \
            _Pragma("unroll")                                                      \
            for (int ni = 0; ni < 4; ni++) {                                       \
                const int c = wn * 32 + ni * 8 + ql * 2;                           \
                const float2 bv = __ldg((const float2*)((bg) + c));                \
                acc[mi][ni][0] = silu_f(acc[mi][ni][0] + bv.x);                    \
                acc[mi][ni][1] = silu_f(acc[mi][ni][1] + bv.y);                    \
                acc[mi][ni][2] = silu_f(acc[mi][ni][2] + bv.x);                    \
                acc[mi][ni][3] = silu_f(acc[mi][ni][3] + bv.y);                    \
            }                                                                      \
        __syncthreads();                                                           \
        store_frag_tf32(As, acc, wm, wn, lane);                                    \
        stage_tf32<128>(Ws, (Wg) + H * H, 128, tid);                               \
        __syncthreads();                                                           \
        gemm_mma<16, 4>(As, Ws, acc, wm, wn, lane);                                \
        _Pragma("unroll")                                                          \
        for (int mi = 0; mi < 2; mi++)                                             \
            _Pragma("unroll")                                                      \
            for (int ni = 0; ni < 4; ni++) {                                       \
                const int c = wn * 32 + ni * 8 + ql * 2;                           \
                const float2 bv = __ldg((const float2*)((bg) + H + c));            \
                frag[mi][ni][0] += silu_f(acc[mi][ni][0] + bv.x);                  \
                frag[mi][ni][1] += silu_f(acc[mi][ni][1] + bv.y);                  \
                frag[mi][ni][2] += silu_f(acc[mi][ni][2] + bv.x);                  \
                frag[mi][ni][3] += silu_f(acc[mi][ni][3] + bv.y);                  \
            }                                                                      \
    }

    // S4: res_before[0]
    RES_BLOCK(res_before_W, res_before_b);

    // S5: e1 = silu(e1 @ W_lin + b) + x_old
    __syncthreads();
    store_frag_tf32(As, frag, wm, wn, lane);
    stage_tf32<128>(Ws, W_lin, 128, tid);
    __syncthreads();
    gemm_mma<16, 4>(As, Ws, acc, wm, wn, lane);
#pragma unroll
    for (int mi = 0; mi < 2; mi++) {
        const int r0 = wm * 32 + mi * 16 + qid;
#pragma unroll
        for (int ni = 0; ni < 4; ni++) {
            const int c = wn * 32 + ni * 8 + ql * 2;
            const float2 bv = __ldg((const float2*)(b_lin + c));
            const float2 x0 = *(const float2*)(Xold + r0 * PA + c);
            const float2 x1v = *(const float2*)(Xold + (r0 + 8) * PA + c);
            frag[mi][ni][0] = silu_f(acc[mi][ni][0] + bv.x) + x0.x;
            frag[mi][ni][1] = silu_f(acc[mi][ni][1] + bv.y) + x0.y;
            frag[mi][ni][2] = silu_f(acc[mi][ni][2] + bv.x) + x1v.x;
            frag[mi][ni][3] = silu_f(acc[mi][ni][3] + bv.y) + x1v.y;
        }
    }

    // S6/S7: res_after[0], res_after[1]
    RES_BLOCK(res_after_W, res_after_b);
    RES_BLOCK(res_after_W + 2 * H * H, res_after_b + 2 * H);

    // S8: write e1; e2 = (rbf0 @ W_rbf) * e1
    {
        const long EH = (long)NE * H;
#pragma unroll
        for (int mi = 0; mi < 2; mi++) {
            const int r0 = wm * 32 + mi * 16 + qid;
#pragma unroll
            for (int ni = 0; ni < 4; ni++) {
                const int c = wn * 32 + ni * 8 + ql * 2;
                float rv[2][2] = {{0.f, 0.f}, {0.f, 0.f}};
#pragma unroll
                for (int l = 0; l < NR; l++) {
                    const float w0 = Wrb[l * 128 + c], w1 = Wrb[l * 128 + c + 1];
                    const float rA = rbs[r0 * 8 + l], rB = rbs[(r0 + 8) * 8 + l];
                    rv[0][0] = fmaf(rA, w0, rv[0][0]); rv[0][1] = fmaf(rA, w1, rv[0][1]);
                    rv[1][0] = fmaf(rB, w0, rv[1][0]); rv[1][1] = fmaf(rB, w1, rv[1][1]);
                }
                const long rowA = (eb + r0) * H + c, rowB = (eb + r0 + 8) * H + c;
                *(float2*)(out + rowA) = make_float2(frag[mi][ni][0], frag[mi][ni][1]);
                *(float2*)(out + rowB) = make_float2(frag[mi][ni][2], frag[mi][ni][3]);
                *(float2*)(out + EH + rowA) =
                    make_float2(rv[0][0] * frag[mi][ni][0], rv[0][1] * frag[mi][ni][1]);
                *(float2*)(out + EH + rowB) =
                    make_float2(rv[1][0] * frag[mi][ni][2], rv[1][1] * frag[mi][ni][3]);
            }
        }
    }
}

// ---------------- launch --------------------------------------------------------
extern "C" void kernel_launch(void* const* d_in, const int* in_sizes, int n_in,
                              void* d_out, int out_size) {
    const float* x1           = (const float*)d_in[0];
    const float* x_old        = (const float*)d_in[1];
    const float* rbf0         = (const float*)d_in[2];
    const float* sbf          = (const float*)d_in[3];
    const int*   idx_kj       = (const int*)d_in[4];
    const int*   idx_ji       = (const int*)d_in[5];
    const float* W_rbf1       = (const float*)d_in[6];
    const float* W_rbf2       = (const float*)d_in[7];
    const float* W_sbf1       = (const float*)d_in[8];
    const float* W_sbf2       = (const float*)d_in[9];
    const float* W_rbf        = (const float*)d_in[10];
    const float* W_kj         = (const float*)d_in[11];
    const float* b_kj         = (const float*)d_in[12];
    const float* W_ji         = (const float*)d_in[13];
    const float* b_ji         = (const float*)d_in[14];
    const float* W_connect    = (const float*)d_in[15];
    const float* b_connect    = (const float*)d_in[16];
    const float* W_get_up     = (const float*)d_in[17];
    const float* b_get_up     = (const float*)d_in[18];
    const float* W_down       = (const float*)d_in[19];
    const float* b_down       = (const float*)d_in[20];
    const float* W_up         = (const float*)d_in[21];
    const float* b_up         = (const float*)d_in[22];
    const float* res_before_W = (const float*)d_in[23];
    const float* res_before_b = (const float*)d_in[24];
    const float* W_lin        = (const float*)d_in[25];
    const float* b_lin        = (const float*)d_in[26];
    const float* res_after_W  = (const float*)d_in[27];
    const float* res_after_b  = (const float*)d_in[28];
    float* out = (float*)d_out;

    cudaFuncSetAttribute(pre_kernel,  cudaFuncAttributeMaxDynamicSharedMemorySize, PRE_SMEM);
    cudaFuncSetAttribute(post_kernel, cudaFuncAttributeMaxDynamicSharedMemorySize, POST_SMEM);

    zero_kernel<<<4096, 256>>>();
    wprep_kernel<<<3, 256>>>(W_rbf1, W_rbf2);
    pre_kernel<<<NE / BM, TPB, PRE_SMEM>>>(x_old, rbf0, W_kj, b_kj, W_down, b_down);
    trip_kernel<<<NT / 32, 256>>>(x1, sbf, idx_kj, idx_ji, W_sbf1, W_sbf2);
    post_kernel<<<NE / BM, TPB, POST_SMEM>>>(
        x_old, rbf0, W_ji, b_ji, W_up, b_up, W_connect, b_connect,
        W_get_up, b_get_up, res_before_W, res_before_b, W_lin, b_lin,
        res_after_W, res_after_b, W_rbf, out);
}